// round 13
// baseline (speedup 1.0000x reference)
#include <cuda_runtime.h>

// Problem constants (fixed by the dataset)
#define NU 500000
#define NI 100000
#define FD 300
#define D  64
#define NE 2000000
#define NL 1000000

// ---------------------------------------------------------------------------
// Device scratch (allocation-free: static __device__ globals)
// ---------------------------------------------------------------------------
__device__ float4 g_xu  [NU * 16];
__device__ float4 g_xi  [NI * 16];
__device__ float4 g_aggu[NU * 16];
__device__ float4 g_aggi[NI * 16];
__device__ float4 g_hu  [NU * 16];
__device__ float4 g_hi  [NI * 16];
__device__ float4 g_pre [NI * 16];   // item features pre-transformed by Wl_iu
__device__ float  g_invu[NU];
__device__ float  g_invi[NI];
__device__ int    g_degu[NU];
__device__ int    g_degi[NI];

// ---------------------------------------------------------------------------
// Packed fp32x2 helpers (sm_100+; ptxas never emits FFMA2 from C++)
// ---------------------------------------------------------------------------
__device__ __forceinline__ unsigned long long pack2(float lo, float hi) {
    unsigned long long r;
    asm("mov.b64 %0, {%1, %2};" : "=l"(r) : "f"(lo), "f"(hi));
    return r;
}
__device__ __forceinline__ void ffma2(unsigned long long& d,
                                      unsigned long long a, unsigned long long b) {
    asm("fma.rn.f32x2 %0, %1, %2, %0;" : "+l"(d) : "l"(a), "l"(b));
}
__device__ __forceinline__ float2 unpack2(unsigned long long v) {
    float2 r;
    asm("mov.b64 {%0, %1}, %2;" : "=f"(r.x), "=f"(r.y) : "l"(v));
    return r;
}

// GEMM tiling: 128 nodes x 64 d per block (256 threads),
// thread tile = 4 nodes x 8 d, k-step 4. LDS bytes/FMA = 1.5.
#define MT 128                 // nodes per block
#define SX_STRIDE 68           // padded row stride (floats)

// Inner-loop macro: consumes sX[MT][SX_STRIDE], sW[64][64] into acc[4][4].
// ig = node-group (4 nodes), j = d-group (8 d).
#define GEMM_INNER(sX, sW, ig, j, acc)                                        \
    _Pragma("unroll")                                                         \
    for (int kk = 0; kk < 16; ++kk) {                                         \
        float4 a0 = *(const float4*)&sX[(ig) * 4 + 0][kk * 4];                \
        float4 a1 = *(const float4*)&sX[(ig) * 4 + 1][kk * 4];                \
        float4 a2 = *(const float4*)&sX[(ig) * 4 + 2][kk * 4];                \
        float4 a3 = *(const float4*)&sX[(ig) * 4 + 3][kk * 4];                \
        _Pragma("unroll")                                                     \
        for (int q = 0; q < 4; ++q) {                                         \
            const int k = kk * 4 + q;                                         \
            ulonglong2 w0 = *(const ulonglong2*)&sW[k][(j) * 8];              \
            ulonglong2 w1 = *(const ulonglong2*)&sW[k][(j) * 8 + 4];          \
            float s0 = q == 0 ? a0.x : q == 1 ? a0.y : q == 2 ? a0.z : a0.w;  \
            float s1 = q == 0 ? a1.x : q == 1 ? a1.y : q == 2 ? a1.z : a1.w;  \
            float s2 = q == 0 ? a2.x : q == 1 ? a2.y : q == 2 ? a2.z : a2.w;  \
            float s3 = q == 0 ? a3.x : q == 1 ? a3.y : q == 2 ? a3.z : a3.w;  \
            unsigned long long p0 = pack2(s0, s0);                            \
            unsigned long long p1 = pack2(s1, s1);                            \
            unsigned long long p2 = pack2(s2, s2);                            \
            unsigned long long p3 = pack2(s3, s3);                            \
            ffma2(acc[0][0], p0, w0.x); ffma2(acc[0][1], p0, w0.y);           \
            ffma2(acc[0][2], p0, w1.x); ffma2(acc[0][3], p0, w1.y);           \
            ffma2(acc[1][0], p1, w0.x); ffma2(acc[1][1], p1, w0.y);           \
            ffma2(acc[1][2], p1, w1.x); ffma2(acc[1][3], p1, w1.y);           \
            ffma2(acc[2][0], p2, w0.x); ffma2(acc[2][1], p2, w0.y);           \
            ffma2(acc[2][2], p2, w1.x); ffma2(acc[2][3], p2, w1.y);           \
            ffma2(acc[3][0], p3, w0.x); ffma2(acc[3][1], p3, w0.y);           \
            ffma2(acc[3][2], p3, w1.x); ffma2(acc[3][3], p3, w1.y);           \
        }                                                                     \
    }

// ---------------------------------------------------------------------------
// Utility kernels
// ---------------------------------------------------------------------------
__global__ void zero_f4(float4* __restrict__ a, int n16) {
    int i = blockIdx.x * blockDim.x + threadIdx.x;
    if (i < n16) a[i] = make_float4(0.f, 0.f, 0.f, 0.f);
}

__global__ void zero_i32(int* __restrict__ a, int n) {
    int i = blockIdx.x * blockDim.x + threadIdx.x;
    if (i < n) a[i] = 0;
}

__global__ void count_deg(const int* __restrict__ src, const int* __restrict__ dst,
                          int* __restrict__ degu, int* __restrict__ degi) {
    int e = blockIdx.x * blockDim.x + threadIdx.x;
    if (e < NE) {
        atomicAdd(&degu[src[e]], 1);
        atomicAdd(&degi[dst[e]], 1);
    }
}

__global__ void make_inv(const int* __restrict__ deg, float* __restrict__ inv, int n) {
    int i = blockIdx.x * blockDim.x + threadIdx.x;
    if (i < n) inv[i] = 1.0f / (float)max(deg[i], 1);
}

__global__ void gather_user(const float4* __restrict__ emb, const int* __restrict__ ids,
                            float4* __restrict__ xu) {
    long t = (long)blockIdx.x * blockDim.x + threadIdx.x;   // NU*16 threads
    if (t >= (long)NU * 16) return;
    int n = (int)(t >> 4), c = (int)(t & 15);
    xu[t] = emb[(long)ids[n] * 16 + c];
}

// ---------------------------------------------------------------------------
// Staging helpers (conflict-free row-major float4 STS)
// ---------------------------------------------------------------------------
__device__ __forceinline__ void stage_nodes(
    float sX[MT][SX_STRIDE], const float4* __restrict__ xin, int nb, int n, int tid)
{
    for (int idx = tid; idx < MT * 16; idx += 256) {
        int nd = idx >> 4, f4 = idx & 15;
        int gn = nb + nd;
        float4 v = make_float4(0.f, 0.f, 0.f, 0.f);
        if (gn < n) v = xin[(long)gn * 16 + f4];
        *(float4*)&sX[nd][f4 * 4] = v;
    }
}

__device__ __forceinline__ void stage_nodes_scaled(
    float sX[MT][SX_STRIDE], const float4* __restrict__ agg,
    const float* __restrict__ inv, int nb, int n, int tid)
{
    for (int idx = tid; idx < MT * 16; idx += 256) {
        int nd = idx >> 4, f4 = idx & 15;
        int gn = nb + nd;
        float4 v = make_float4(0.f, 0.f, 0.f, 0.f);
        if (gn < n) {
            v = agg[(long)gn * 16 + f4];
            float s = inv[gn];
            v.x *= s; v.y *= s; v.z *= s; v.w *= s;
        }
        *(float4*)&sX[nd][f4 * 4] = v;
    }
}

__device__ __forceinline__ void stage_w(
    float sW[64][64], const float* __restrict__ W, int tid)
{
    for (int idx = tid; idx < 64 * 16; idx += 256) {
        *(float4*)&sW[0][idx * 4] = ((const float4*)W)[idx];
    }
}

// ---------------------------------------------------------------------------
// Item input linear: out[NI,64] = X[NI,300] @ W[300,64] + b
// ---------------------------------------------------------------------------
__global__ __launch_bounds__(256) void item_linear(
    const float* __restrict__ X, const float* __restrict__ W,
    const float* __restrict__ bias, float4* __restrict__ out)
{
    __shared__ float sX[MT][SX_STRIDE];
    __shared__ float sW[64][64];
    const int tid = threadIdx.x;
    const int ig = tid >> 3;   // node group (4 nodes)
    const int j  = tid & 7;    // d group (8 channels)
    const int ib = blockIdx.x * MT;

    unsigned long long acc[4][4] = {};

    for (int c = 0; c < 5; ++c) {                // 5 chunks of 64 cover K=300
        const int k0 = c * 64;
        const int nf4 = min(16, 75 - c * 16);    // valid float4s (300/4 = 75)

        for (int idx = tid; idx < MT * 16; idx += 256) {
            int it = idx >> 4, f4 = idx & 15;
            int gi = ib + it;
            float4 v = make_float4(0.f, 0.f, 0.f, 0.f);
            if (gi < NI && f4 < nf4)
                v = *(const float4*)&X[(long)gi * FD + k0 + f4 * 4];
            *(float4*)&sX[it][f4 * 4] = v;
        }
        for (int idx = tid; idx < 64 * 16; idx += 256) {
            int k = idx >> 4, f4 = idx & 15;
            float4 v = make_float4(0.f, 0.f, 0.f, 0.f);
            if (k0 + k < FD)
                v = *(const float4*)&W[(long)(k0 + k) * D + f4 * 4];
            *(float4*)&sW[k][f4 * 4] = v;
        }
        __syncthreads();
        GEMM_INNER(sX, sW, ig, j, acc)
        __syncthreads();
    }

    float4 b0 = __ldg((const float4*)&bias[j * 8]);
    float4 b1 = __ldg((const float4*)&bias[j * 8 + 4]);
    #pragma unroll
    for (int m = 0; m < 4; ++m) {
        int gi = ib + ig * 4 + m;
        if (gi < NI) {
            float2 v0 = unpack2(acc[m][0]), v1 = unpack2(acc[m][1]);
            float2 v2 = unpack2(acc[m][2]), v3 = unpack2(acc[m][3]);
            out[(long)gi * 16 + j * 2]     = make_float4(v0.x + b0.x, v0.y + b0.y, v1.x + b0.z, v1.y + b0.w);
            out[(long)gi * 16 + j * 2 + 1] = make_float4(v2.x + b1.x, v2.y + b1.y, v3.x + b1.z, v3.y + b1.w);
        }
    }
}

// ---------------------------------------------------------------------------
// Plain GEMM: out[n,64] = x[n,64] @ W   (item pre-transform)
// ---------------------------------------------------------------------------
__global__ __launch_bounds__(256) void gemm64(
    const float4* __restrict__ xin, const float* __restrict__ W,
    float4* __restrict__ out, int n)
{
    __shared__ float sX[MT][SX_STRIDE];
    __shared__ float sW[64][64];
    const int tid = threadIdx.x;
    const int ig = tid >> 3;
    const int j  = tid & 7;
    const int nb = blockIdx.x * MT;

    unsigned long long acc[4][4] = {};

    stage_nodes(sX, xin, nb, n, tid);
    stage_w(sW, W, tid);
    __syncthreads();
    GEMM_INNER(sX, sW, ig, j, acc)

    #pragma unroll
    for (int m = 0; m < 4; ++m) {
        int gn = nb + ig * 4 + m;
        if (gn < n) {
            float2 v0 = unpack2(acc[m][0]), v1 = unpack2(acc[m][1]);
            float2 v2 = unpack2(acc[m][2]), v3 = unpack2(acc[m][3]);
            out[(long)gn * 16 + j * 2]     = make_float4(v0.x, v0.y, v1.x, v1.y);
            out[(long)gn * 16 + j * 2 + 1] = make_float4(v2.x, v2.y, v3.x, v3.y);
        }
    }
}

// ---------------------------------------------------------------------------
// User update (transform-first aggregation):
//   out[n] = relu_opt( agg[n]*inv[n] + bias + xin[n] @ Wr )
// ---------------------------------------------------------------------------
__global__ __launch_bounds__(256) void user_update(
    const float4* __restrict__ agg, const float* __restrict__ inv,
    const float4* __restrict__ xin, const float* __restrict__ Wr,
    const float* __restrict__ bias, float4* __restrict__ out, int n, int relu)
{
    __shared__ float sX[MT][SX_STRIDE];
    __shared__ float sW[64][64];
    const int tid = threadIdx.x;
    const int ig = tid >> 3;
    const int j  = tid & 7;
    const int nb = blockIdx.x * MT;

    unsigned long long acc[4][4] = {};

    stage_nodes(sX, xin, nb, n, tid);
    stage_w(sW, Wr, tid);
    __syncthreads();
    GEMM_INNER(sX, sW, ig, j, acc)

    float4 b0 = __ldg((const float4*)&bias[j * 8]);
    float4 b1 = __ldg((const float4*)&bias[j * 8 + 4]);
    #pragma unroll
    for (int m = 0; m < 4; ++m) {
        int gn = nb + ig * 4 + m;
        if (gn < n) {
            float s = inv[gn];
            float4 g0 = agg[(long)gn * 16 + j * 2];
            float4 g1 = agg[(long)gn * 16 + j * 2 + 1];
            float2 v0 = unpack2(acc[m][0]), v1 = unpack2(acc[m][1]);
            float2 v2 = unpack2(acc[m][2]), v3 = unpack2(acc[m][3]);
            float4 r0 = make_float4(v0.x + b0.x + g0.x * s, v0.y + b0.y + g0.y * s,
                                    v1.x + b0.z + g0.z * s, v1.y + b0.w + g0.w * s);
            float4 r1 = make_float4(v2.x + b1.x + g1.x * s, v2.y + b1.y + g1.y * s,
                                    v3.x + b1.z + g1.z * s, v3.y + b1.w + g1.w * s);
            if (relu) {
                r0.x = fmaxf(r0.x, 0.f); r0.y = fmaxf(r0.y, 0.f);
                r0.z = fmaxf(r0.z, 0.f); r0.w = fmaxf(r0.w, 0.f);
                r1.x = fmaxf(r1.x, 0.f); r1.y = fmaxf(r1.y, 0.f);
                r1.z = fmaxf(r1.z, 0.f); r1.w = fmaxf(r1.w, 0.f);
            }
            out[(long)gn * 16 + j * 2]     = r0;
            out[(long)gn * 16 + j * 2 + 1] = r1;
        }
    }
}

// ---------------------------------------------------------------------------
// Item update (aggregate-then-transform, two matmuls):
//   out[n] = relu_opt( (agg[n]*inv[n]) @ Wl + bias + xin[n] @ Wr )
// ---------------------------------------------------------------------------
__global__ __launch_bounds__(256) void sage_update(
    const float4* __restrict__ agg, const float* __restrict__ inv,
    const float4* __restrict__ xin, const float* __restrict__ Wl,
    const float* __restrict__ Wr, const float* __restrict__ bias,
    float4* __restrict__ out, int n, int relu)
{
    __shared__ float sX[MT][SX_STRIDE];
    __shared__ float sW[64][64];
    const int tid = threadIdx.x;
    const int ig = tid >> 3;
    const int j  = tid & 7;
    const int nb = blockIdx.x * MT;

    unsigned long long acc[4][4] = {};

    // phase 0: mean-aggregate @ Wl
    stage_nodes_scaled(sX, agg, inv, nb, n, tid);
    stage_w(sW, Wl, tid);
    __syncthreads();
    GEMM_INNER(sX, sW, ig, j, acc)
    __syncthreads();

    // phase 1: x @ Wr
    stage_nodes(sX, xin, nb, n, tid);
    stage_w(sW, Wr, tid);
    __syncthreads();
    GEMM_INNER(sX, sW, ig, j, acc)

    float4 b0 = __ldg((const float4*)&bias[j * 8]);
    float4 b1 = __ldg((const float4*)&bias[j * 8 + 4]);
    #pragma unroll
    for (int m = 0; m < 4; ++m) {
        int gn = nb + ig * 4 + m;
        if (gn < n) {
            float2 v0 = unpack2(acc[m][0]), v1 = unpack2(acc[m][1]);
            float2 v2 = unpack2(acc[m][2]), v3 = unpack2(acc[m][3]);
            float4 r0 = make_float4(v0.x + b0.x, v0.y + b0.y, v1.x + b0.z, v1.y + b0.w);
            float4 r1 = make_float4(v2.x + b1.x, v2.y + b1.y, v3.x + b1.z, v3.y + b1.w);
            if (relu) {
                r0.x = fmaxf(r0.x, 0.f); r0.y = fmaxf(r0.y, 0.f);
                r0.z = fmaxf(r0.z, 0.f); r0.w = fmaxf(r0.w, 0.f);
                r1.x = fmaxf(r1.x, 0.f); r1.y = fmaxf(r1.y, 0.f);
                r1.z = fmaxf(r1.z, 0.f); r1.w = fmaxf(r1.w, 0.f);
            }
            out[(long)gn * 16 + j * 2]     = r0;
            out[(long)gn * 16 + j * 2 + 1] = r1;
        }
    }
}

// ---------------------------------------------------------------------------
// Edge scatter-add: agg[dst] += x[src]. 16 threads/edge, float4 reads,
// one red.global.add.v4.f32 per thread.
// ---------------------------------------------------------------------------
__device__ __forceinline__ void red_add_v4(float* addr, float4 v) {
    asm volatile("red.global.add.v4.f32 [%0], {%1, %2, %3, %4};"
                 :: "l"(addr), "f"(v.x), "f"(v.y), "f"(v.z), "f"(v.w)
                 : "memory");
}

__global__ void scatter_add(const float4* __restrict__ x,
                            const int* __restrict__ sidx,
                            const int* __restrict__ didx,
                            float* __restrict__ agg)
{
    long t = (long)blockIdx.x * blockDim.x + threadIdx.x;   // NE*16 threads
    if (t >= (long)NE * 16) return;
    int e = (int)(t >> 4), c = (int)(t & 15);
    int s = sidx[e], d2 = didx[e];
    float4 v = x[(long)s * 16 + c];
    red_add_v4(agg + (long)d2 * 64 + c * 4, v);
}

// ---------------------------------------------------------------------------
// Predictor: out[e] = dot64(hu[ls[e]], hi[ld[e]]). 8 threads/edge.
// ---------------------------------------------------------------------------
__global__ void edge_dot(const float4* __restrict__ hu, const float4* __restrict__ hi,
                         const int* __restrict__ ls, const int* __restrict__ ld,
                         float* __restrict__ out)
{
    long t = (long)blockIdx.x * blockDim.x + threadIdx.x;   // NL*8 threads (exact)
    int e = (int)(t >> 3), c = (int)(t & 7);
    long ub = (long)ls[e] * 16 + c * 2;
    long ib = (long)ld[e] * 16 + c * 2;
    float4 a0 = hu[ub], a1 = hu[ub + 1];
    float4 b0 = hi[ib], b1 = hi[ib + 1];
    float p = a0.x * b0.x + a0.y * b0.y + a0.z * b0.z + a0.w * b0.w
            + a1.x * b1.x + a1.y * b1.y + a1.z * b1.z + a1.w * b1.w;
    p += __shfl_xor_sync(0xffffffffu, p, 4);
    p += __shfl_xor_sync(0xffffffffu, p, 2);
    p += __shfl_xor_sync(0xffffffffu, p, 1);
    if (c == 0) out[e] = p;
}

// ---------------------------------------------------------------------------
// Launch. ncu capture lands on OUR 0-based launch #3 -> item_linear
// (clean A/B of the restructured GEMM vs round 12's profile).
// ---------------------------------------------------------------------------
extern "C" void kernel_launch(void* const* d_in, const int* in_sizes, int n_in,
                              void* d_out, int out_size)
{
    const float* user_emb_w = (const float*)d_in[0];
    const float* item_x     = (const float*)d_in[1];
    const float* item_lin_w = (const float*)d_in[2];
    const float* item_lin_b = (const float*)d_in[3];
    const float* Wl1_ui = (const float*)d_in[4];
    const float* Wr1_ui = (const float*)d_in[5];
    const float* b1_ui  = (const float*)d_in[6];
    const float* Wl1_iu = (const float*)d_in[7];
    const float* Wr1_iu = (const float*)d_in[8];
    const float* b1_iu  = (const float*)d_in[9];
    const float* Wl2_ui = (const float*)d_in[10];
    const float* Wr2_ui = (const float*)d_in[11];
    const float* b2_ui  = (const float*)d_in[12];
    const float* Wl2_iu = (const float*)d_in[13];
    const float* Wr2_iu = (const float*)d_in[14];
    const float* b2_iu  = (const float*)d_in[15];
    const int* user_node_id = (const int*)d_in[16];
    const int* edge_src  = (const int*)d_in[17];
    const int* edge_dst  = (const int*)d_in[18];
    const int* label_src = (const int*)d_in[19];
    const int* label_dst = (const int*)d_in[20];
    float* out = (float*)d_out;

    float4 *xu, *xi, *aggu, *aggi, *hu, *hi, *pre;
    float *invu, *invi;
    int *degu, *degi;
    cudaGetSymbolAddress((void**)&xu,   g_xu);
    cudaGetSymbolAddress((void**)&xi,   g_xi);
    cudaGetSymbolAddress((void**)&aggu, g_aggu);
    cudaGetSymbolAddress((void**)&aggi, g_aggi);
    cudaGetSymbolAddress((void**)&hu,   g_hu);
    cudaGetSymbolAddress((void**)&hi,   g_hi);
    cudaGetSymbolAddress((void**)&pre,  g_pre);
    cudaGetSymbolAddress((void**)&invu, g_invu);
    cudaGetSymbolAddress((void**)&invi, g_invi);
    cudaGetSymbolAddress((void**)&degu, g_degu);
    cudaGetSymbolAddress((void**)&degi, g_degi);

    const int T = 256;
    const int gNU16 = (NU * 16) / T;              // 31250
    const int gNI16 = (NI * 16) / T;              // 6250
    const int gE16  = (int)(((long)NE * 16) / T); // 125000
    const int gNI128 = (NI + MT - 1) / MT;        // 782
    const int gNU128 = (NU + MT - 1) / MT;        // 3907

    // [0..2]: independent setup
    gather_user<<<gNU16, T>>>((const float4*)user_emb_w, user_node_id, xu);          // 0
    zero_f4<<<gNU16, T>>>(aggu, NU * 16);                                            // 1
    zero_f4<<<gNI16, T>>>(aggi, NI * 16);                                            // 2

    // [3]: item_linear (PROFILED launch — representative GEMM)
    item_linear<<<gNI128, T>>>(item_x, item_lin_w, item_lin_b, xi);                  // 3

    // degrees + means
    zero_i32<<<(NU + T - 1) / T, T>>>(degu, NU);
    zero_i32<<<(NI + T - 1) / T, T>>>(degi, NI);
    count_deg<<<(NE + T - 1) / T, T>>>(edge_src, edge_dst, degu, degi);
    make_inv<<<(NU + T - 1) / T, T>>>(degu, invu, NU);
    make_inv<<<(NI + T - 1) / T, T>>>(degi, invi, NI);

    // ---- layer 1 ----
    // user side: transform-first (pre = xi @ Wl1_iu), scatter, 1-matmul update
    gemm64<<<gNI128, T>>>(xi, Wl1_iu, pre, NI);
    scatter_add<<<gE16, T>>>(pre, edge_dst, edge_src, (float*)aggu);  // items -> users
    user_update<<<gNU128, T>>>(aggu, invu, xu, Wr1_iu, b1_iu, hu, NU, 1);
    // item side: aggregate-then-transform
    scatter_add<<<gE16, T>>>(xu, edge_src, edge_dst, (float*)aggi);   // users -> items
    sage_update<<<gNI128, T>>>(aggi, invi, xi, Wl1_ui, Wr1_ui, b1_ui, hi, NI, 1);

    // ---- layer 2 ---- (reuse xu/xi as layer-2 outputs)
    zero_f4<<<gNU16, T>>>(aggu, NU * 16);
    gemm64<<<gNI128, T>>>(hi, Wl2_iu, pre, NI);
    scatter_add<<<gE16, T>>>(pre, edge_dst, edge_src, (float*)aggu);
    user_update<<<gNU128, T>>>(aggu, invu, hu, Wr2_iu, b2_iu, xu, NU, 0);
    zero_f4<<<gNI16, T>>>(aggi, NI * 16);
    scatter_add<<<gE16, T>>>(hu, edge_src, edge_dst, (float*)aggi);
    sage_update<<<gNI128, T>>>(aggi, invi, hi, Wl2_ui, Wr2_ui, b2_ui, xi, NI, 0);

    // ---- predictor ----
    edge_dot<<<(int)(((long)NL * 8) / T), T>>>(xu, xi, label_src, label_dst, out);
}

// round 14
// speedup vs baseline: 1.1990x; 1.1990x over previous
#include <cuda_runtime.h>

// Problem constants (fixed by the dataset)
#define NU 500000
#define NI 100000
#define FD 300
#define D  64
#define NE 2000000
#define NL 1000000

// ---------------------------------------------------------------------------
// Device scratch (allocation-free: static __device__ globals)
// ---------------------------------------------------------------------------
__device__ float4 g_xu  [NU * 16];
__device__ float4 g_xi  [NI * 16];
__device__ float4 g_aggu[NU * 16];
__device__ float4 g_aggi[NI * 16];
__device__ float4 g_hu  [NU * 16];
__device__ float4 g_hi  [NI * 16];
__device__ float4 g_pre [NI * 16];   // item features pre-transformed by Wl_iu
__device__ float  g_invu[NU];
__device__ float  g_invi[NI];
__device__ int    g_degu[NU];
__device__ int    g_degi[NI];

// ---------------------------------------------------------------------------
// Packed fp32x2 helpers (sm_100+; ptxas never emits FFMA2 from C++)
// ---------------------------------------------------------------------------
__device__ __forceinline__ unsigned long long pack2(float lo, float hi) {
    unsigned long long r;
    asm("mov.b64 %0, {%1, %2};" : "=l"(r) : "f"(lo), "f"(hi));
    return r;
}
__device__ __forceinline__ void ffma2(unsigned long long& d,
                                      unsigned long long a, unsigned long long b) {
    asm("fma.rn.f32x2 %0, %1, %2, %0;" : "+l"(d) : "l"(a), "l"(b));
}
__device__ __forceinline__ float2 unpack2(unsigned long long v) {
    float2 r;
    asm("mov.b64 {%0, %1}, %2;" : "=f"(r.x), "=f"(r.y) : "l"(v));
    return r;
}

// GEMM tiling (same shape as the 1263us R12 kernel): 64 nodes x 64 d per
// block (256 threads), thread tile = 4 nodes x 4 d, ~16 acc regs.
// Activation smem layout is k-interleaved float4: sX4[f4][node], stride 65.
//  - staging: one STS.128 per thread, conflict-free per quarter-warp
//  - inner loop: LDS.128 per node per 4-k block + 16B w per k, conflict-free
#define MT 64                  // nodes per block
#define SX4_STRIDE 65          // float4 row stride for sX4

// Inner loop: consumes sX4[16][SX4_STRIDE] (float4) and sW[64][64] into
// acc[4][2] (packed fp32x2 pairs). ig = node group (4 nodes), j = d group (4 d).
#define GEMM_INNER(sX4, sW, ig, j, acc)                                       \
    _Pragma("unroll")                                                         \
    for (int kk = 0; kk < 16; ++kk) {                                         \
        float4 a0 = sX4[kk][(ig) * 4 + 0];                                    \
        float4 a1 = sX4[kk][(ig) * 4 + 1];                                    \
        float4 a2 = sX4[kk][(ig) * 4 + 2];                                    \
        float4 a3 = sX4[kk][(ig) * 4 + 3];                                    \
        _Pragma("unroll")                                                     \
        for (int q = 0; q < 4; ++q) {                                         \
            const int k = kk * 4 + q;                                         \
            ulonglong2 w = *(const ulonglong2*)&sW[k][(j) * 4];               \
            float s0 = q == 0 ? a0.x : q == 1 ? a0.y : q == 2 ? a0.z : a0.w;  \
            float s1 = q == 0 ? a1.x : q == 1 ? a1.y : q == 2 ? a1.z : a1.w;  \
            float s2 = q == 0 ? a2.x : q == 1 ? a2.y : q == 2 ? a2.z : a2.w;  \
            float s3 = q == 0 ? a3.x : q == 1 ? a3.y : q == 2 ? a3.z : a3.w;  \
            unsigned long long p0 = pack2(s0, s0);                            \
            unsigned long long p1 = pack2(s1, s1);                            \
            unsigned long long p2 = pack2(s2, s2);                            \
            unsigned long long p3 = pack2(s3, s3);                            \
            ffma2(acc[0][0], p0, w.x); ffma2(acc[0][1], p0, w.y);             \
            ffma2(acc[1][0], p1, w.x); ffma2(acc[1][1], p1, w.y);             \
            ffma2(acc[2][0], p2, w.x); ffma2(acc[2][1], p2, w.y);             \
            ffma2(acc[3][0], p3, w.x); ffma2(acc[3][1], p3, w.y);             \
        }                                                                     \
    }

// ---------------------------------------------------------------------------
// Utility kernels
// ---------------------------------------------------------------------------
__global__ void zero_f4(float4* __restrict__ a, int n16) {
    int i = blockIdx.x * blockDim.x + threadIdx.x;
    if (i < n16) a[i] = make_float4(0.f, 0.f, 0.f, 0.f);
}

__global__ void zero_i32(int* __restrict__ a, int n) {
    int i = blockIdx.x * blockDim.x + threadIdx.x;
    if (i < n) a[i] = 0;
}

__global__ void count_deg(const int* __restrict__ src, const int* __restrict__ dst,
                          int* __restrict__ degu, int* __restrict__ degi) {
    int e = blockIdx.x * blockDim.x + threadIdx.x;
    if (e < NE) {
        atomicAdd(&degu[src[e]], 1);
        atomicAdd(&degi[dst[e]], 1);
    }
}

__global__ void make_inv(const int* __restrict__ deg, float* __restrict__ inv, int n) {
    int i = blockIdx.x * blockDim.x + threadIdx.x;
    if (i < n) inv[i] = 1.0f / (float)max(deg[i], 1);
}

__global__ void gather_user(const float4* __restrict__ emb, const int* __restrict__ ids,
                            float4* __restrict__ xu) {
    long t = (long)blockIdx.x * blockDim.x + threadIdx.x;   // NU*16 threads
    if (t >= (long)NU * 16) return;
    int n = (int)(t >> 4), c = (int)(t & 15);
    xu[t] = emb[(long)ids[n] * 16 + c];
}

// ---------------------------------------------------------------------------
// Staging helpers. sX4[f4][node]: thread (node=idx>>4, f4=idx&15) does one
// float4 gmem read (coalesced: 16 lanes cover one 256B node row) and one
// STS.128 — bank-group (f4 + node) mod 8, distinct within each quarter-warp.
// ---------------------------------------------------------------------------
__device__ __forceinline__ void stage_nodes(
    float4 sX4[16][SX4_STRIDE], const float4* __restrict__ xin, int nb, int n, int tid)
{
    for (int idx = tid; idx < MT * 16; idx += 256) {
        int nd = idx >> 4, f4 = idx & 15;
        int gn = nb + nd;
        float4 v = make_float4(0.f, 0.f, 0.f, 0.f);
        if (gn < n) v = xin[(long)gn * 16 + f4];
        sX4[f4][nd] = v;
    }
}

__device__ __forceinline__ void stage_nodes_scaled(
    float4 sX4[16][SX4_STRIDE], const float4* __restrict__ agg,
    const float* __restrict__ inv, int nb, int n, int tid)
{
    for (int idx = tid; idx < MT * 16; idx += 256) {
        int nd = idx >> 4, f4 = idx & 15;
        int gn = nb + nd;
        float4 v = make_float4(0.f, 0.f, 0.f, 0.f);
        if (gn < n) {
            v = agg[(long)gn * 16 + f4];
            float s = inv[gn];
            v.x *= s; v.y *= s; v.z *= s; v.w *= s;
        }
        sX4[f4][nd] = v;
    }
}

__device__ __forceinline__ void stage_w(
    float sW[64][64], const float* __restrict__ W, int tid)
{
    for (int idx = tid; idx < 64 * 16; idx += 256) {
        int k = idx >> 4, f4 = idx & 15;
        *(float4*)&sW[k][f4 * 4] = ((const float4*)W)[idx];
    }
}

// ---------------------------------------------------------------------------
// Item input linear: out[NI,64] = X[NI,300] @ W[300,64] + b
// ---------------------------------------------------------------------------
__global__ __launch_bounds__(256) void item_linear(
    const float* __restrict__ X, const float* __restrict__ W,
    const float* __restrict__ bias, float4* __restrict__ out)
{
    __shared__ float4 sX4[16][SX4_STRIDE];
    __shared__ float sW[64][64];
    const int tid = threadIdx.x;
    const int ig = tid >> 4;   // node group (4 nodes)
    const int j  = tid & 15;   // d group (4 channels)
    const int ib = blockIdx.x * MT;

    unsigned long long acc[4][2] = {};

    for (int c = 0; c < 5; ++c) {                // 5 chunks of 64 cover K=300
        const int k0 = c * 64;
        const int nf4 = min(16, 75 - c * 16);    // valid float4s (300/4 = 75)

        for (int idx = tid; idx < MT * 16; idx += 256) {
            int it = idx >> 4, f4 = idx & 15;
            int gi = ib + it;
            float4 v = make_float4(0.f, 0.f, 0.f, 0.f);
            if (gi < NI && f4 < nf4)
                v = *(const float4*)&X[(long)gi * FD + k0 + f4 * 4];
            sX4[f4][it] = v;
        }
        for (int idx = tid; idx < 64 * 16; idx += 256) {
            int k = idx >> 4, f4 = idx & 15;
            float4 v = make_float4(0.f, 0.f, 0.f, 0.f);
            if (k0 + k < FD)
                v = *(const float4*)&W[(long)(k0 + k) * D + f4 * 4];
            *(float4*)&sW[k][f4 * 4] = v;
        }
        __syncthreads();
        GEMM_INNER(sX4, sW, ig, j, acc)
        __syncthreads();
    }

    float4 b = __ldg((const float4*)&bias[j * 4]);
    #pragma unroll
    for (int m = 0; m < 4; ++m) {
        int gi = ib + ig * 4 + m;
        if (gi < NI) {
            float2 lo = unpack2(acc[m][0]), hi = unpack2(acc[m][1]);
            out[(long)gi * 16 + j] = make_float4(lo.x + b.x, lo.y + b.y,
                                                 hi.x + b.z, hi.y + b.w);
        }
    }
}

// ---------------------------------------------------------------------------
// Plain GEMM: out[n,64] = x[n,64] @ W   (item pre-transform)
// ---------------------------------------------------------------------------
__global__ __launch_bounds__(256) void gemm64(
    const float4* __restrict__ xin, const float* __restrict__ W,
    float4* __restrict__ out, int n)
{
    __shared__ float4 sX4[16][SX4_STRIDE];
    __shared__ float sW[64][64];
    const int tid = threadIdx.x;
    const int ig = tid >> 4;
    const int j  = tid & 15;
    const int nb = blockIdx.x * MT;

    unsigned long long acc[4][2] = {};

    stage_nodes(sX4, xin, nb, n, tid);
    stage_w(sW, W, tid);
    __syncthreads();
    GEMM_INNER(sX4, sW, ig, j, acc)

    #pragma unroll
    for (int m = 0; m < 4; ++m) {
        int gn = nb + ig * 4 + m;
        if (gn < n) {
            float2 lo = unpack2(acc[m][0]), hi = unpack2(acc[m][1]);
            out[(long)gn * 16 + j] = make_float4(lo.x, lo.y, hi.x, hi.y);
        }
    }
}

// ---------------------------------------------------------------------------
// User update (transform-first aggregation):
//   out[n] = relu_opt( agg[n]*inv[n] + bias + xin[n] @ Wr )
// ---------------------------------------------------------------------------
__global__ __launch_bounds__(256) void user_update(
    const float4* __restrict__ agg, const float* __restrict__ inv,
    const float4* __restrict__ xin, const float* __restrict__ Wr,
    const float* __restrict__ bias, float4* __restrict__ out, int n, int relu)
{
    __shared__ float4 sX4[16][SX4_STRIDE];
    __shared__ float sW[64][64];
    const int tid = threadIdx.x;
    const int ig = tid >> 4;
    const int j  = tid & 15;
    const int nb = blockIdx.x * MT;

    unsigned long long acc[4][2] = {};

    stage_nodes(sX4, xin, nb, n, tid);
    stage_w(sW, Wr, tid);
    __syncthreads();
    GEMM_INNER(sX4, sW, ig, j, acc)

    float4 b = __ldg((const float4*)&bias[j * 4]);
    #pragma unroll
    for (int m = 0; m < 4; ++m) {
        int gn = nb + ig * 4 + m;
        if (gn < n) {
            float s = inv[gn];
            float4 g = agg[(long)gn * 16 + j];
            float2 lo = unpack2(acc[m][0]), hi = unpack2(acc[m][1]);
            float4 r = make_float4(lo.x + b.x + g.x * s, lo.y + b.y + g.y * s,
                                   hi.x + b.z + g.z * s, hi.y + b.w + g.w * s);
            if (relu) {
                r.x = fmaxf(r.x, 0.f); r.y = fmaxf(r.y, 0.f);
                r.z = fmaxf(r.z, 0.f); r.w = fmaxf(r.w, 0.f);
            }
            out[(long)gn * 16 + j] = r;
        }
    }
}

// ---------------------------------------------------------------------------
// Item update (aggregate-then-transform, two matmuls):
//   out[n] = relu_opt( (agg[n]*inv[n]) @ Wl + bias + xin[n] @ Wr )
// ---------------------------------------------------------------------------
__global__ __launch_bounds__(256) void sage_update(
    const float4* __restrict__ agg, const float* __restrict__ inv,
    const float4* __restrict__ xin, const float* __restrict__ Wl,
    const float* __restrict__ Wr, const float* __restrict__ bias,
    float4* __restrict__ out, int n, int relu)
{
    __shared__ float4 sX4[16][SX4_STRIDE];
    __shared__ float sW[64][64];
    const int tid = threadIdx.x;
    const int ig = tid >> 4;
    const int j  = tid & 15;
    const int nb = blockIdx.x * MT;

    unsigned long long acc[4][2] = {};

    // phase 0: mean-aggregate @ Wl
    stage_nodes_scaled(sX4, agg, inv, nb, n, tid);
    stage_w(sW, Wl, tid);
    __syncthreads();
    GEMM_INNER(sX4, sW, ig, j, acc)
    __syncthreads();

    // phase 1: x @ Wr
    stage_nodes(sX4, xin, nb, n, tid);
    stage_w(sW, Wr, tid);
    __syncthreads();
    GEMM_INNER(sX4, sW, ig, j, acc)

    float4 b = __ldg((const float4*)&bias[j * 4]);
    #pragma unroll
    for (int m = 0; m < 4; ++m) {
        int gn = nb + ig * 4 + m;
        if (gn < n) {
            float2 lo = unpack2(acc[m][0]), hi = unpack2(acc[m][1]);
            float4 r = make_float4(lo.x + b.x, lo.y + b.y, hi.x + b.z, hi.y + b.w);
            if (relu) {
                r.x = fmaxf(r.x, 0.f); r.y = fmaxf(r.y, 0.f);
                r.z = fmaxf(r.z, 0.f); r.w = fmaxf(r.w, 0.f);
            }
            out[(long)gn * 16 + j] = r;
        }
    }
}

// ---------------------------------------------------------------------------
// Edge scatter-add: agg[dst] += x[src]. 16 threads/edge, float4 reads,
// one red.global.add.v4.f32 per thread.
// ---------------------------------------------------------------------------
__device__ __forceinline__ void red_add_v4(float* addr, float4 v) {
    asm volatile("red.global.add.v4.f32 [%0], {%1, %2, %3, %4};"
                 :: "l"(addr), "f"(v.x), "f"(v.y), "f"(v.z), "f"(v.w)
                 : "memory");
}

__global__ void scatter_add(const float4* __restrict__ x,
                            const int* __restrict__ sidx,
                            const int* __restrict__ didx,
                            float* __restrict__ agg)
{
    long t = (long)blockIdx.x * blockDim.x + threadIdx.x;   // NE*16 threads
    if (t >= (long)NE * 16) return;
    int e = (int)(t >> 4), c = (int)(t & 15);
    int s = sidx[e], d2 = didx[e];
    float4 v = x[(long)s * 16 + c];
    red_add_v4(agg + (long)d2 * 64 + c * 4, v);
}

// ---------------------------------------------------------------------------
// Predictor: out[e] = dot64(hu[ls[e]], hi[ld[e]]). 8 threads/edge.
// ---------------------------------------------------------------------------
__global__ void edge_dot(const float4* __restrict__ hu, const float4* __restrict__ hi,
                         const int* __restrict__ ls, const int* __restrict__ ld,
                         float* __restrict__ out)
{
    long t = (long)blockIdx.x * blockDim.x + threadIdx.x;   // NL*8 threads (exact)
    int e = (int)(t >> 3), c = (int)(t & 7);
    long ub = (long)ls[e] * 16 + c * 2;
    long ib = (long)ld[e] * 16 + c * 2;
    float4 a0 = hu[ub], a1 = hu[ub + 1];
    float4 b0 = hi[ib], b1 = hi[ib + 1];
    float p = a0.x * b0.x + a0.y * b0.y + a0.z * b0.z + a0.w * b0.w
            + a1.x * b1.x + a1.y * b1.y + a1.z * b1.z + a1.w * b1.w;
    p += __shfl_xor_sync(0xffffffffu, p, 4);
    p += __shfl_xor_sync(0xffffffffu, p, 2);
    p += __shfl_xor_sync(0xffffffffu, p, 1);
    if (c == 0) out[e] = p;
}

// ---------------------------------------------------------------------------
// Launch. ncu capture lands on OUR 0-based launch #3 -> item_linear
// (A/B of the conflict-free staging vs rounds 12/13).
// ---------------------------------------------------------------------------
extern "C" void kernel_launch(void* const* d_in, const int* in_sizes, int n_in,
                              void* d_out, int out_size)
{
    const float* user_emb_w = (const float*)d_in[0];
    const float* item_x     = (const float*)d_in[1];
    const float* item_lin_w = (const float*)d_in[2];
    const float* item_lin_b = (const float*)d_in[3];
    const float* Wl1_ui = (const float*)d_in[4];
    const float* Wr1_ui = (const float*)d_in[5];
    const float* b1_ui  = (const float*)d_in[6];
    const float* Wl1_iu = (const float*)d_in[7];
    const float* Wr1_iu = (const float*)d_in[8];
    const float* b1_iu  = (const float*)d_in[9];
    const float* Wl2_ui = (const float*)d_in[10];
    const float* Wr2_ui = (const float*)d_in[11];
    const float* b2_ui  = (const float*)d_in[12];
    const float* Wl2_iu = (const float*)d_in[13];
    const float* Wr2_iu = (const float*)d_in[14];
    const float* b2_iu  = (const float*)d_in[15];
    const int* user_node_id = (const int*)d_in[16];
    const int* edge_src  = (const int*)d_in[17];
    const int* edge_dst  = (const int*)d_in[18];
    const int* label_src = (const int*)d_in[19];
    const int* label_dst = (const int*)d_in[20];
    float* out = (float*)d_out;

    float4 *xu, *xi, *aggu, *aggi, *hu, *hi, *pre;
    float *invu, *invi;
    int *degu, *degi;
    cudaGetSymbolAddress((void**)&xu,   g_xu);
    cudaGetSymbolAddress((void**)&xi,   g_xi);
    cudaGetSymbolAddress((void**)&aggu, g_aggu);
    cudaGetSymbolAddress((void**)&aggi, g_aggi);
    cudaGetSymbolAddress((void**)&hu,   g_hu);
    cudaGetSymbolAddress((void**)&hi,   g_hi);
    cudaGetSymbolAddress((void**)&pre,  g_pre);
    cudaGetSymbolAddress((void**)&invu, g_invu);
    cudaGetSymbolAddress((void**)&invi, g_invi);
    cudaGetSymbolAddress((void**)&degu, g_degu);
    cudaGetSymbolAddress((void**)&degi, g_degi);

    const int T = 256;
    const int gNU16 = (NU * 16) / T;              // 31250
    const int gNI16 = (NI * 16) / T;              // 6250
    const int gE16  = (int)(((long)NE * 16) / T); // 125000
    const int gNI64 = (NI + MT - 1) / MT;
    const int gNU64 = (NU + MT - 1) / MT;

    // [0..2]: independent setup
    gather_user<<<gNU16, T>>>((const float4*)user_emb_w, user_node_id, xu);          // 0
    zero_f4<<<gNU16, T>>>(aggu, NU * 16);                                            // 1
    zero_f4<<<gNI16, T>>>(aggi, NI * 16);                                            // 2

    // [3]: item_linear (PROFILED launch — representative GEMM)
    item_linear<<<gNI64, T>>>(item_x, item_lin_w, item_lin_b, xi);                   // 3

    // degrees + means
    zero_i32<<<(NU + T - 1) / T, T>>>(degu, NU);
    zero_i32<<<(NI + T - 1) / T, T>>>(degi, NI);
    count_deg<<<(NE + T - 1) / T, T>>>(edge_src, edge_dst, degu, degi);
    make_inv<<<(NU + T - 1) / T, T>>>(degu, invu, NU);
    make_inv<<<(NI + T - 1) / T, T>>>(degi, invi, NI);

    // ---- layer 1 ----
    // user side: transform-first (pre = xi @ Wl1_iu), scatter, 1-matmul update
    gemm64<<<gNI64, T>>>(xi, Wl1_iu, pre, NI);
    scatter_add<<<gE16, T>>>(pre, edge_dst, edge_src, (float*)aggu);  // items -> users
    user_update<<<gNU64, T>>>(aggu, invu, xu, Wr1_iu, b1_iu, hu, NU, 1);
    // item side: aggregate-then-transform
    scatter_add<<<gE16, T>>>(xu, edge_src, edge_dst, (float*)aggi);   // users -> items
    sage_update<<<gNI64, T>>>(aggi, invi, xi, Wl1_ui, Wr1_ui, b1_ui, hi, NI, 1);

    // ---- layer 2 ---- (reuse xu/xi as layer-2 outputs)
    zero_f4<<<gNU16, T>>>(aggu, NU * 16);
    gemm64<<<gNI64, T>>>(hi, Wl2_iu, pre, NI);
    scatter_add<<<gE16, T>>>(pre, edge_dst, edge_src, (float*)aggu);
    user_update<<<gNU64, T>>>(aggu, invu, hu, Wr2_iu, b2_iu, xu, NU, 0);
    zero_f4<<<gNI16, T>>>(aggi, NI * 16);
    scatter_add<<<gE16, T>>>(hu, edge_src, edge_dst, (float*)aggi);
    sage_update<<<gNI64, T>>>(aggi, invi, hi, Wl2_ui, Wr2_ui, b2_ui, xi, NI, 0);

    // ---- predictor ----
    edge_dot<<<(int)(((long)NL * 8) / T), T>>>(xu, xi, label_src, label_dst, out);
}